// round 1
// baseline (speedup 1.0000x reference)
#include <cuda_runtime.h>
#include <cuda_bf16.h>
#include <math.h>

// Problem constants (B,S,D fixed by the dataset)
#define BB 8
#define SS 1024
#define DD 512
#define HH 8
#define DKK 64
#define MM (BB*SS)   // 8192 rows

// Scratch (static __device__ arrays: allocation-guard safe)
__device__ float g_Q[(size_t)MM * DD];
__device__ float g_K[(size_t)MM * DD];
__device__ float g_V[(size_t)MM * DD];
__device__ float g_O[(size_t)MM * DD];

// ---------------------------------------------------------------------------
// GEMM: C[M,512] = A[M,512] @ W[512,512] + bias (+ resid). 64x64x16 tiles,
// 256 threads, 4x4 micro-tile, float4 smem traffic.
// ---------------------------------------------------------------------------
#define GTK 16

__global__ __launch_bounds__(256) void gemm_bias_kernel(
    const float* __restrict__ A, const float* __restrict__ W,
    const float* __restrict__ bias, const float* __restrict__ resid,
    float* __restrict__ C)
{
    __shared__ float At[GTK][68];
    __shared__ float Wt[GTK][68];
    const int tid = threadIdx.x;
    const int tx = tid & 15, ty = tid >> 4;
    const int bm = blockIdx.y * 64, bn = blockIdx.x * 64;

    const int ar = tid >> 2;          // 0..63
    const int ac = (tid & 3) * 4;     // 0,4,8,12
    const int wr = tid >> 4;          // 0..15
    const int wc = (tid & 15) * 4;    // 0..60

    float acc[4][4] = {};

    for (int k0 = 0; k0 < DD; k0 += GTK) {
        float4 av = *(const float4*)(A + (size_t)(bm + ar) * DD + (k0 + ac));
        At[ac + 0][ar] = av.x;
        At[ac + 1][ar] = av.y;
        At[ac + 2][ar] = av.z;
        At[ac + 3][ar] = av.w;
        *(float4*)&Wt[wr][wc] = *(const float4*)(W + (size_t)(k0 + wr) * DD + (bn + wc));
        __syncthreads();
#pragma unroll
        for (int kk = 0; kk < GTK; kk++) {
            float a[4], b[4];
            *(float4*)a = *(const float4*)&At[kk][ty * 4];
            *(float4*)b = *(const float4*)&Wt[kk][tx * 4];
#pragma unroll
            for (int i = 0; i < 4; i++)
#pragma unroll
                for (int j = 0; j < 4; j++)
                    acc[i][j] += a[i] * b[j];
        }
        __syncthreads();
    }

    float4 bb = *(const float4*)(bias + bn + tx * 4);
#pragma unroll
    for (int i = 0; i < 4; i++) {
        const size_t row = (size_t)(bm + ty * 4 + i);
        float4 o;
        o.x = acc[i][0] + bb.x;
        o.y = acc[i][1] + bb.y;
        o.z = acc[i][2] + bb.z;
        o.w = acc[i][3] + bb.w;
        if (resid) {
            float4 rv = *(const float4*)(resid + row * DD + bn + tx * 4);
            o.x += rv.x; o.y += rv.y; o.z += rv.z; o.w += rv.w;
        }
        *(float4*)(C + row * DD + bn + tx * 4) = o;
    }
}

// ---------------------------------------------------------------------------
// Fused dual-score causal attention with online softmax.
// Block = (b,h, 64 query rows). 256 threads, 4x4 micro-tiles for 64x64 tiles.
//   s1 = (Q@K^T)/8                          (projected)
//   s2 = (qraw@kraw^T) * te_h / sqrt(512)   (raw, gated by state_mask)
//   score = j<i ? s1 + (mask? s2:0) : -inf
// Online softmax; row with zero valid keys (row 0) outputs 0 (matches ref).
// ---------------------------------------------------------------------------
#define PADW 68
#define ATT_SMEM (6 * 64 * PADW * sizeof(float))   // 104448 bytes

extern __shared__ float as_mem[];

__global__ __launch_bounds__(256) void attn_kernel(
    const float* __restrict__ Qp, const float* __restrict__ Kp,
    const float* __restrict__ Vp,
    const float* __restrict__ qraw, const float* __restrict__ kraw,
    const int* __restrict__ smask, const float* __restrict__ gammas,
    float* __restrict__ Op)
{
    float* Qt  = as_mem;              // [kk][r]
    float* Qrt = Qt  + 64 * PADW;     // [kk][r]
    float* Kt  = Qrt + 64 * PADW;     // [kk][c]
    float* Krt = Kt  + 64 * PADW;     // [kk][c]
    float* Vs  = Krt + 64 * PADW;     // [c][d]
    float* Ps  = Vs  + 64 * PADW;     // [r][c]

    const int tid = threadIdx.x;
    const int tx = tid & 15, ty = tid >> 4;
    const int q0 = blockIdx.x * 64;
    const int b  = blockIdx.y / HH;
    const int h  = blockIdx.y % HH;
    const int hc = h * DKK;

    // total_effect for this head: clip(exp(-softplus(gamma)), 1e-5, 1e5)
    float g  = gammas[h];
    float sp = (g > 20.f) ? g : log1pf(__expf(g));
    float te = __expf(-sp);
    te = fminf(fmaxf(te, 1e-5f), 1e5f);
    const float f2 = te * rsqrtf((float)DD);   // raw-score factor
    const float f1 = rsqrtf((float)DKK);       // 1/8

    // Load Q tiles (transposed into smem)
    const int lr = tid >> 2;          // row 0..63
    const int lc = (tid & 3) * 4;     // 0..12
    {
        const size_t qb = ((size_t)(b * SS + q0 + lr)) * DD + hc;
#pragma unroll
        for (int p = 0; p < 4; p++) {
            const int c = p * 16 + lc;
            float4 v  = *(const float4*)(Qp   + qb + c);
            float4 vr = *(const float4*)(qraw + qb + c);
            Qt [(c + 0) * PADW + lr] = v.x;  Qt [(c + 1) * PADW + lr] = v.y;
            Qt [(c + 2) * PADW + lr] = v.z;  Qt [(c + 3) * PADW + lr] = v.w;
            Qrt[(c + 0) * PADW + lr] = vr.x; Qrt[(c + 1) * PADW + lr] = vr.y;
            Qrt[(c + 2) * PADW + lr] = vr.z; Qrt[(c + 3) * PADW + lr] = vr.w;
        }
    }

    float mrow[4], lrow[4], acc[4][4];
#pragma unroll
    for (int i = 0; i < 4; i++) {
        mrow[i] = -1e30f; lrow[i] = 0.f;
#pragma unroll
        for (int j = 0; j < 4; j++) acc[i][j] = 0.f;
    }

    const int gi0 = q0 + ty * 4;

    for (int kt0 = 0; kt0 <= q0; kt0 += 64) {
        __syncthreads();   // protect Vs/Ps from previous iteration
        {
            const size_t kb = ((size_t)(b * SS + kt0 + lr)) * DD + hc;
#pragma unroll
            for (int p = 0; p < 4; p++) {
                const int c = p * 16 + lc;
                float4 v  = *(const float4*)(Kp   + kb + c);
                float4 vr = *(const float4*)(kraw + kb + c);
                float4 vv = *(const float4*)(Vp   + kb + c);
                Kt [(c + 0) * PADW + lr] = v.x;  Kt [(c + 1) * PADW + lr] = v.y;
                Kt [(c + 2) * PADW + lr] = v.z;  Kt [(c + 3) * PADW + lr] = v.w;
                Krt[(c + 0) * PADW + lr] = vr.x; Krt[(c + 1) * PADW + lr] = vr.y;
                Krt[(c + 2) * PADW + lr] = vr.z; Krt[(c + 3) * PADW + lr] = vr.w;
                *(float4*)&Vs[lr * PADW + c] = vv;
            }
        }
        __syncthreads();

        // Both score GEMMs in one kk-loop
        float s1[4][4] = {}, s2[4][4] = {};
#pragma unroll 16
        for (int kk = 0; kk < DKK; kk++) {
            float qa[4], qr[4], ka[4], kr[4];
            *(float4*)qa = *(const float4*)&Qt [kk * PADW + ty * 4];
            *(float4*)qr = *(const float4*)&Qrt[kk * PADW + ty * 4];
            *(float4*)ka = *(const float4*)&Kt [kk * PADW + tx * 4];
            *(float4*)kr = *(const float4*)&Krt[kk * PADW + tx * 4];
#pragma unroll
            for (int i = 0; i < 4; i++)
#pragma unroll
                for (int j = 0; j < 4; j++) {
                    s1[i][j] += qa[i] * ka[j];
                    s2[i][j] += qr[i] * kr[j];
                }
        }

        // Mask + online softmax update
        const int gj0 = kt0 + tx * 4;
        float p[4][4], scl[4];
#pragma unroll
        for (int i = 0; i < 4; i++) {
            const int gi = gi0 + i;
            float sc[4];
            bool  vd[4];
            float rm = -1e30f;
#pragma unroll
            for (int j = 0; j < 4; j++) {
                const int gj = gj0 + j;
                const bool valid = (gj < gi);
                float s = -1e30f;
                if (valid) {
                    s = s1[i][j] * f1;
                    const int mv = smask[((size_t)b * SS + gi) * SS + gj];
                    if (mv) s += s2[i][j] * f2;
                    rm = fmaxf(rm, s);
                }
                sc[j] = s; vd[j] = valid;
            }
            rm = fmaxf(rm, __shfl_xor_sync(0xffffffffu, rm, 1));
            rm = fmaxf(rm, __shfl_xor_sync(0xffffffffu, rm, 2));
            rm = fmaxf(rm, __shfl_xor_sync(0xffffffffu, rm, 4));
            rm = fmaxf(rm, __shfl_xor_sync(0xffffffffu, rm, 8));
            const float mn = fmaxf(mrow[i], rm);
            float rs = 0.f;
#pragma unroll
            for (int j = 0; j < 4; j++) {
                const float pv = vd[j] ? __expf(sc[j] - mn) : 0.f;
                p[i][j] = pv; rs += pv;
            }
            rs += __shfl_xor_sync(0xffffffffu, rs, 1);
            rs += __shfl_xor_sync(0xffffffffu, rs, 2);
            rs += __shfl_xor_sync(0xffffffffu, rs, 4);
            rs += __shfl_xor_sync(0xffffffffu, rs, 8);
            const float s_old = __expf(mrow[i] - mn);  // exp(0)=1 when both sentinel: harmless, acc=l=0
            mrow[i] = mn;
            lrow[i] = lrow[i] * s_old + rs;
            scl[i]  = s_old;
        }

        // Rescale accumulator, stage P into smem
#pragma unroll
        for (int i = 0; i < 4; i++) {
#pragma unroll
            for (int j = 0; j < 4; j++) acc[i][j] *= scl[i];
            float4 pv = make_float4(p[i][0], p[i][1], p[i][2], p[i][3]);
            *(float4*)&Ps[(ty * 4 + i) * PADW + tx * 4] = pv;
        }
        __syncthreads();

        // O += P @ V
#pragma unroll 16
        for (int c = 0; c < 64; c++) {
            float4 vb = *(const float4*)&Vs[c * PADW + tx * 4];
#pragma unroll
            for (int i = 0; i < 4; i++) {
                const float a = Ps[(ty * 4 + i) * PADW + c];
                acc[i][0] += a * vb.x;
                acc[i][1] += a * vb.y;
                acc[i][2] += a * vb.z;
                acc[i][3] += a * vb.w;
            }
        }
    }

    // Normalize + write out (row with no valid keys -> 0, matches reference)
#pragma unroll
    for (int i = 0; i < 4; i++) {
        const float r = (lrow[i] > 0.f) ? (1.f / lrow[i]) : 0.f;
        float4 o = make_float4(acc[i][0] * r, acc[i][1] * r, acc[i][2] * r, acc[i][3] * r);
        *(float4*)(Op + ((size_t)(b * SS + gi0 + i)) * DD + hc + tx * 4) = o;
    }
}

// ---------------------------------------------------------------------------
// In-place LayerNorm: one warp per row of 512 floats.
// ---------------------------------------------------------------------------
__global__ __launch_bounds__(256) void ln_kernel(
    float* __restrict__ X, const float* __restrict__ gam, const float* __restrict__ bet)
{
    const int warp = threadIdx.x >> 5, lane = threadIdx.x & 31;
    const size_t row = (size_t)blockIdx.x * 8 + warp;
    float* xr = X + row * DD;

    float4 v[4];
    float s = 0.f, s2 = 0.f;
#pragma unroll
    for (int w = 0; w < 4; w++) {
        v[w] = *(const float4*)(xr + w * 128 + lane * 4);
        s  += v[w].x + v[w].y + v[w].z + v[w].w;
        s2 += v[w].x * v[w].x + v[w].y * v[w].y + v[w].z * v[w].z + v[w].w * v[w].w;
    }
#pragma unroll
    for (int o = 16; o > 0; o >>= 1) {
        s  += __shfl_xor_sync(0xffffffffu, s,  o);
        s2 += __shfl_xor_sync(0xffffffffu, s2, o);
    }
    const float mu  = s * (1.f / DD);
    const float var = s2 * (1.f / DD) - mu * mu;
    const float inv = rsqrtf(var + 1e-5f);
#pragma unroll
    for (int w = 0; w < 4; w++) {
        const int c = w * 128 + lane * 4;
        float4 gv = *(const float4*)(gam + c);
        float4 bv = *(const float4*)(bet + c);
        float4 o;
        o.x = (v[w].x - mu) * inv * gv.x + bv.x;
        o.y = (v[w].y - mu) * inv * gv.y + bv.y;
        o.z = (v[w].z - mu) * inv * gv.z + bv.z;
        o.w = (v[w].w - mu) * inv * gv.w + bv.w;
        *(float4*)(xr + c) = o;
    }
}

// ---------------------------------------------------------------------------
extern "C" void kernel_launch(void* const* d_in, const int* in_sizes, int n_in,
                              void* d_out, int out_size)
{
    const float* q_in  = (const float*)d_in[0];
    const float* k_in  = (const float*)d_in[1];
    const float* v_in  = (const float*)d_in[2];
    const int*   smask = (const int*)  d_in[3];
    const float* Wq    = (const float*)d_in[4];
    const float* bq    = (const float*)d_in[5];
    const float* Wv    = (const float*)d_in[6];
    const float* bv    = (const float*)d_in[7];
    const float* Wo    = (const float*)d_in[8];
    const float* bo    = (const float*)d_in[9];
    const float* gam   = (const float*)d_in[10];
    const float* ln_g  = (const float*)d_in[11];
    const float* ln_b  = (const float*)d_in[12];
    float* out = (float*)d_out;

    float *Qb, *Kb, *Vb, *Ob;
    cudaGetSymbolAddress((void**)&Qb, g_Q);
    cudaGetSymbolAddress((void**)&Kb, g_K);
    cudaGetSymbolAddress((void**)&Vb, g_V);
    cudaGetSymbolAddress((void**)&Ob, g_O);

    cudaFuncSetAttribute(attn_kernel, cudaFuncAttributeMaxDynamicSharedMemorySize,
                         (int)ATT_SMEM);

    dim3 gb(256);
    dim3 gemm_grid(DD / 64, MM / 64);   // (8, 128)

    // Q/K/V projections
    gemm_bias_kernel<<<gemm_grid, gb>>>(q_in, Wq, bq, nullptr, Qb);
    gemm_bias_kernel<<<gemm_grid, gb>>>(k_in, Wq, bq, nullptr, Kb);
    gemm_bias_kernel<<<gemm_grid, gb>>>(v_in, Wv, bv, nullptr, Vb);

    // Fused attention
    dim3 agrid(SS / 64, BB * HH);       // (16, 64)
    attn_kernel<<<agrid, gb, ATT_SMEM>>>(Qb, Kb, Vb, q_in, k_in, smask, gam, Ob);

    // Output projection + bias + residual into d_out
    gemm_bias_kernel<<<gemm_grid, gb>>>(Ob, Wo, bo, q_in, out);

    // In-place LayerNorm
    ln_kernel<<<MM / 8, gb>>>(out, ln_g, ln_b);
}